// round 8
// baseline (speedup 1.0000x reference)
#include <cuda_runtime.h>
#include <math.h>
#include <stdint.h>

#define S_DIM 128
#define R_DIM 256
#define C_DIM 256
#define H_DIM 8
#define D_DIM 32
#define HD_DIM 256
#define SR_DIM (S_DIM * R_DIM)

// Scratch (device globals; allocation-free contract)
__device__ float g_Q[S_DIM * H_DIM * R_DIM * D_DIM];   // [s][h][r][d]
__device__ float g_K[S_DIM * H_DIM * R_DIM * D_DIM];
__device__ float g_V[S_DIM * H_DIM * R_DIM * D_DIM];
__device__ float g_G[S_DIM * H_DIM * R_DIM * D_DIM];
__device__ float g_O[S_DIM * H_DIM * R_DIM * D_DIM];   // gated: O * G
__device__ float g_biasT[H_DIM * R_DIM * R_DIM];       // [h][q][k]

// ---------------------------------------------------------------------------
// helpers
// ---------------------------------------------------------------------------
__device__ __forceinline__ uint32_t f2tf(float f) {
    uint32_t u;
    asm("cvt.rna.tf32.f32 %0, %1;" : "=r"(u) : "f"(f));
    return u;
}

__device__ __forceinline__ void mma_tf32(float c[4],
                                         uint32_t a0, uint32_t a1,
                                         uint32_t a2, uint32_t a3,
                                         uint32_t b0, uint32_t b1) {
    asm volatile(
        "mma.sync.aligned.m16n8k8.row.col.f32.tf32.tf32.f32 "
        "{%0,%1,%2,%3}, {%4,%5,%6,%7}, {%8,%9}, {%0,%1,%2,%3};"
        : "+f"(c[0]), "+f"(c[1]), "+f"(c[2]), "+f"(c[3])
        : "r"(a0), "r"(a1), "r"(a2), "r"(a3), "r"(b0), "r"(b1));
}

__device__ __forceinline__ void cp16(uint32_t smem_addr, const void* gptr) {
    asm volatile("cp.async.cg.shared.global [%0], [%1], 16;"
                 :: "r"(smem_addr), "l"(gptr));
}
__device__ __forceinline__ void cp_commit() {
    asm volatile("cp.async.commit_group;");
}
template <int N>
__device__ __forceinline__ void cp_wait() {
    asm volatile("cp.async.wait_group %0;" :: "n"(N));
}

// GEMM tiling: block 64(M) x 256(N), BK=32, 4 warps of 64x64.
// A stride 36 (bank = 4*gid+tid, conflict-free), B stride 264 (bank =
// 8*tid+gid, conflict-free).
#define AS_STRIDE 36
#define BS_STRIDE 264
#define AS_WORDS (64 * AS_STRIDE)    // 2304
#define BS_WORDS (32 * BS_STRIDE)    // 8448
#define GEMM_SMEM_BYTES ((2 * AS_WORDS + 2 * BS_WORDS) * 4)  // 86016

// ---------------------------------------------------------------------------
// Kernel 1: bias [q][k][h] -> biasT [h][q][k]
// ---------------------------------------------------------------------------
__global__ void bias_transpose_kernel(const float* __restrict__ bias) {
    int idx = blockIdx.x * blockDim.x + threadIdx.x;
    if (idx < H_DIM * R_DIM * R_DIM) {
        int k  = idx & 255;
        int qq = (idx >> 8) & 255;
        int h  = idx >> 16;
        g_biasT[idx] = bias[((qq << 8) + k) * 8 + h];
    }
}

// ---------------------------------------------------------------------------
// GEMM core: per-kt fragment MMA loop shared by proj/outproj.
// Each warp: 64x64 tile = 4 m16 x 8 n8, 4 k-steps of 8.
// ---------------------------------------------------------------------------
__device__ __forceinline__ void gemm_chunk(const uint32_t* __restrict__ As,
                                           const uint32_t* __restrict__ Bs,
                                           int w, int gid, int tid,
                                           float acc[4][8][4]) {
#pragma unroll
    for (int ks = 0; ks < 4; ks++) {
        int kk = ks * 8;
        uint32_t af[4][4], bf[8][2];
#pragma unroll
        for (int i = 0; i < 4; i++) {
            int r0 = i * 16;
            af[i][0] = As[(r0 + gid) * AS_STRIDE + kk + tid];
            af[i][1] = As[(r0 + gid + 8) * AS_STRIDE + kk + tid];
            af[i][2] = As[(r0 + gid) * AS_STRIDE + kk + tid + 4];
            af[i][3] = As[(r0 + gid + 8) * AS_STRIDE + kk + tid + 4];
        }
#pragma unroll
        for (int j = 0; j < 8; j++) {
            int c0 = w * 64 + j * 8 + gid;
            bf[j][0] = Bs[(kk + tid) * BS_STRIDE + c0];
            bf[j][1] = Bs[(kk + tid + 4) * BS_STRIDE + c0];
        }
#pragma unroll
        for (int i = 0; i < 4; i++)
#pragma unroll
            for (int j = 0; j < 8; j++)
                mma_tf32(acc[i][j], af[i][0], af[i][1], af[i][2], af[i][3],
                         bf[j][0], bf[j][1]);
    }
}

// ---------------------------------------------------------------------------
// Kernel 2: fused projections, cp.async double-buffered tf32 MMA.
// C[M=32768,N=256] = A[M,256] * W[256,256]; y: 0=Q(*norm) 1=K 2=V 3=G(sigmoid)
// ---------------------------------------------------------------------------
__global__ void __launch_bounds__(128)
proj_mma_kernel(const float* __restrict__ qin,
                const float* __restrict__ kvin,
                const float* __restrict__ w_q,
                const float* __restrict__ w_k,
                const float* __restrict__ w_v,
                const float* __restrict__ w_g,
                const float* __restrict__ b_g) {
    extern __shared__ uint32_t smem[];
    uint32_t* Asm = smem;                    // 2 x [64][36]
    uint32_t* Bsm = smem + 2 * AS_WORDS;     // 2 x [32][264]

    int type = blockIdx.y;
    const float* A = (type == 1 || type == 2) ? kvin : qin;
    const float* W = (type == 0) ? w_q : (type == 1) ? w_k
                   : (type == 2) ? w_v : w_g;
    float* Out = (type == 0) ? g_Q : (type == 1) ? g_K
               : (type == 2) ? g_V : g_G;

    int t = threadIdx.x;
    int bM = blockIdx.x * 64;
    int lane = t & 31, w = t >> 5;           // 4 warps, warpN = w
    int gid = lane >> 2, tid = lane & 3;

    uint32_t asBase = (uint32_t)__cvta_generic_to_shared(Asm);
    uint32_t bsBase = (uint32_t)__cvta_generic_to_shared(Bsm);

    auto issue = [&](int kt, int buf) {
        int kc = kt * 32;
#pragma unroll
        for (int p = 0; p < 4; p++) {        // A: 64x32 = 512 float4
            int idx = t + p * 128;
            int row = idx >> 3, c4 = (idx & 7) * 4;
            cp16(asBase + (buf * AS_WORDS + row * AS_STRIDE + c4) * 4,
                 A + (bM + row) * 256 + kc + c4);
        }
#pragma unroll
        for (int p = 0; p < 16; p++) {       // B: 32x256 = 2048 float4
            int idx = t + p * 128;
            int br = idx >> 6, bc = (idx & 63) * 4;
            cp16(bsBase + (buf * BS_WORDS + br * BS_STRIDE + bc) * 4,
                 W + (kc + br) * 256 + bc);
        }
        cp_commit();
    };

    float acc[4][8][4];
#pragma unroll
    for (int i = 0; i < 4; i++)
#pragma unroll
        for (int j = 0; j < 8; j++)
#pragma unroll
            for (int r = 0; r < 4; r++) acc[i][j][r] = 0.f;

    issue(0, 0);

    for (int kt = 0; kt < 8; kt++) {
        int cur = kt & 1;
        if (kt < 7) { issue(kt + 1, cur ^ 1); cp_wait<1>(); }
        else        { cp_wait<0>(); }
        __syncthreads();
        gemm_chunk(Asm + cur * AS_WORDS, Bsm + cur * BS_WORDS,
                   w, gid, tid, acc);
        __syncthreads();
    }

    float norm = 0.17677669529663687f;  // 1/sqrt(32)
#pragma unroll
    for (int i = 0; i < 4; i++) {
#pragma unroll
        for (int j = 0; j < 8; j++) {
            int r0 = bM + i * 16 + gid;
            int c0 = w * 64 + j * 8 + tid * 2;
#pragma unroll
            for (int e = 0; e < 4; e++) {
                int row = r0 + (e >> 1) * 8;
                int col = c0 + (e & 1);
                float v = acc[i][j][e];
                if (type == 0) v *= norm;
                if (type == 3) v = 1.f / (1.f + __expf(-(v + b_g[col])));
                int s = row >> 8, rr = row & 255;
                int h = col >> 5, d = col & 31;
                Out[((s * 8 + h) * 256 + rr) * 32 + d] = v;
            }
        }
    }
}

// ---------------------------------------------------------------------------
// Kernel 3: tensor-core attention + fused G gating (unchanged from R7).
// ---------------------------------------------------------------------------
#define ATTN_SMEM_WORDS (9216 + 8320 + 17408 + 256)   // Ks + Vt + Ps + Mb

__global__ void __launch_bounds__(256)
attn_mma_kernel(const float* __restrict__ bias_mask) {
    extern __shared__ uint32_t sm[];
    uint32_t* Ks = sm;                 // [256][36] tf32 K (key, d)
    uint32_t* Vt = sm + 9216;          // [32][260] tf32 V^T (d, key)
    uint32_t* Ps = sm + 17536;         // 8 warps x [32][68] tf32 P
    float*    Mb = (float*)(sm + 34944);  // [256] mask bias

    int s = blockIdx.x, h = blockIdx.y;
    int t = threadIdx.x, lane = t & 31, w = t >> 5;
    int gid = lane >> 2, tid = lane & 3;

    const float* Qg = g_Q + (s * 8 + h) * 8192;
    const float* Kg = g_K + (s * 8 + h) * 8192;
    const float* Vg = g_V + (s * 8 + h) * 8192;
    const float* Gg = g_G + (s * 8 + h) * 8192;

    uint32_t* Qs = Ps;
#pragma unroll
    for (int i = t; i < 2048; i += 256) {
        float4 v = ((const float4*)Qg)[i];
        int r = i >> 3, d = (i & 7) * 4;
        Qs[r * 36 + d + 0] = f2tf(v.x);
        Qs[r * 36 + d + 1] = f2tf(v.y);
        Qs[r * 36 + d + 2] = f2tf(v.z);
        Qs[r * 36 + d + 3] = f2tf(v.w);
    }
    __syncthreads();

    uint32_t qf[2][4][4];
#pragma unroll
    for (int i2 = 0; i2 < 2; i2++) {
        int r0 = w * 32 + i2 * 16;
#pragma unroll
        for (int ks = 0; ks < 4; ks++) {
            int kk = ks * 8;
            qf[i2][ks][0] = Qs[(r0 + gid) * 36 + kk + tid];
            qf[i2][ks][1] = Qs[(r0 + gid + 8) * 36 + kk + tid];
            qf[i2][ks][2] = Qs[(r0 + gid) * 36 + kk + tid + 4];
            qf[i2][ks][3] = Qs[(r0 + gid + 8) * 36 + kk + tid + 4];
        }
    }
    __syncthreads();

#pragma unroll
    for (int i = t; i < 2048; i += 256) {
        int r = i >> 3, d = (i & 7) * 4;
        float4 kv = ((const float4*)Kg)[i];
        Ks[r * 36 + d + 0] = f2tf(kv.x);
        Ks[r * 36 + d + 1] = f2tf(kv.y);
        Ks[r * 36 + d + 2] = f2tf(kv.z);
        Ks[r * 36 + d + 3] = f2tf(kv.w);
        float4 vv = ((const float4*)Vg)[i];
        Vt[(d + 0) * 260 + r] = f2tf(vv.x);
        Vt[(d + 1) * 260 + r] = f2tf(vv.y);
        Vt[(d + 2) * 260 + r] = f2tf(vv.z);
        Vt[(d + 3) * 260 + r] = f2tf(vv.w);
    }
    Mb[t] = (bias_mask[s * 256 + t] - 1.f) * 1e9f;
    __syncthreads();

    const float* biasBase = g_biasT + h * 65536;
    uint32_t* Pw = Ps + w * 2176;

    float oacc[2][4][4];
#pragma unroll
    for (int i2 = 0; i2 < 2; i2++)
#pragma unroll
        for (int j2 = 0; j2 < 4; j2++)
#pragma unroll
            for (int e = 0; e < 4; e++) oacc[i2][j2][e] = 0.f;
    float rs[2][2] = {{0.f, 0.f}, {0.f, 0.f}};

    for (int kc = 0; kc < 256; kc += 64) {
        float sacc[2][8][4];
#pragma unroll
        for (int i2 = 0; i2 < 2; i2++)
#pragma unroll
            for (int j = 0; j < 8; j++)
#pragma unroll
                for (int e = 0; e < 4; e++) sacc[i2][j][e] = 0.f;

#pragma unroll
        for (int ks = 0; ks < 4; ks++) {
            int kk = ks * 8;
            uint32_t bf[8][2];
#pragma unroll
            for (int j = 0; j < 8; j++) {
                int n = kc + j * 8 + gid;
                bf[j][0] = Ks[n * 36 + kk + tid];
                bf[j][1] = Ks[n * 36 + kk + tid + 4];
            }
#pragma unroll
            for (int i2 = 0; i2 < 2; i2++)
#pragma unroll
                for (int j = 0; j < 8; j++)
                    mma_tf32(sacc[i2][j], qf[i2][ks][0], qf[i2][ks][1],
                             qf[i2][ks][2], qf[i2][ks][3], bf[j][0], bf[j][1]);
        }

#pragma unroll
        for (int i2 = 0; i2 < 2; i2++) {
            int qrow = w * 32 + i2 * 16 + gid;
#pragma unroll
            for (int j = 0; j < 8; j++) {
                int col = kc + j * 8 + tid * 2;
                float2 b0 = *(const float2*)(biasBase + qrow * 256 + col);
                float2 b1 = *(const float2*)(biasBase + (qrow + 8) * 256 + col);
                float m0 = Mb[col], m1 = Mb[col + 1];
                float p0 = __expf(sacc[i2][j][0] + b0.x + m0);
                float p1 = __expf(sacc[i2][j][1] + b0.y + m1);
                float p2 = __expf(sacc[i2][j][2] + b1.x + m0);
                float p3 = __expf(sacc[i2][j][3] + b1.y + m1);
                rs[i2][0] += p0 + p1;
                rs[i2][1] += p2 + p3;
                int lr = i2 * 16 + gid, lc = j * 8 + tid * 2;
                Pw[lr * 68 + lc]           = f2tf(p0);
                Pw[lr * 68 + lc + 1]       = f2tf(p1);
                Pw[(lr + 8) * 68 + lc]     = f2tf(p2);
                Pw[(lr + 8) * 68 + lc + 1] = f2tf(p3);
            }
        }
        __syncwarp();

#pragma unroll
        for (int ks2 = 0; ks2 < 8; ks2++) {
            int kk = ks2 * 8;
            uint32_t pf[2][4];
#pragma unroll
            for (int i2 = 0; i2 < 2; i2++) {
                int lr = i2 * 16 + gid;
                pf[i2][0] = Pw[lr * 68 + kk + tid];
                pf[i2][1] = Pw[(lr + 8) * 68 + kk + tid];
                pf[i2][2] = Pw[lr * 68 + kk + tid + 4];
                pf[i2][3] = Pw[(lr + 8) * 68 + kk + tid + 4];
            }
            uint32_t vf[4][2];
#pragma unroll
            for (int j2 = 0; j2 < 4; j2++) {
                int d = j2 * 8 + gid;
                vf[j2][0] = Vt[d * 260 + kc + kk + tid];
                vf[j2][1] = Vt[d * 260 + kc + kk + tid + 4];
            }
#pragma unroll
            for (int i2 = 0; i2 < 2; i2++)
#pragma unroll
                for (int j2 = 0; j2 < 4; j2++)
                    mma_tf32(oacc[i2][j2], pf[i2][0], pf[i2][1],
                             pf[i2][2], pf[i2][3], vf[j2][0], vf[j2][1]);
        }
        __syncwarp();
    }

#pragma unroll
    for (int i2 = 0; i2 < 2; i2++)
#pragma unroll
        for (int rp = 0; rp < 2; rp++) {
            float v = rs[i2][rp];
            v += __shfl_xor_sync(0xffffffffu, v, 1);
            v += __shfl_xor_sync(0xffffffffu, v, 2);
            rs[i2][rp] = 1.f / v;
        }

    float* Og = g_O + (s * 8 + h) * 8192;
#pragma unroll
    for (int i2 = 0; i2 < 2; i2++) {
        int r0 = w * 32 + i2 * 16 + gid;
#pragma unroll
        for (int j2 = 0; j2 < 4; j2++) {
            int c = j2 * 8 + tid * 2;
            float2 gv0 = *(const float2*)(Gg + r0 * 32 + c);
            float2 gv1 = *(const float2*)(Gg + (r0 + 8) * 32 + c);
            Og[r0 * 32 + c]           = oacc[i2][j2][0] * rs[i2][0] * gv0.x;
            Og[r0 * 32 + c + 1]       = oacc[i2][j2][1] * rs[i2][0] * gv0.y;
            Og[(r0 + 8) * 32 + c]     = oacc[i2][j2][2] * rs[i2][1] * gv1.x;
            Og[(r0 + 8) * 32 + c + 1] = oacc[i2][j2][3] * rs[i2][1] * gv1.y;
        }
    }
}

// ---------------------------------------------------------------------------
// Kernel 4: out = g_O(gated) @ Wo + b_o, same 64x256 tiling.
// ---------------------------------------------------------------------------
__global__ void __launch_bounds__(128)
outproj_mma_kernel(const float* __restrict__ w_o,
                   const float* __restrict__ b_o,
                   float* __restrict__ out) {
    extern __shared__ uint32_t smem[];
    uint32_t* Asm = smem;
    uint32_t* Bsm = smem + 2 * AS_WORDS;

    int t = threadIdx.x;
    int bM = blockIdx.x * 64;
    int lane = t & 31, w = t >> 5;
    int gid = lane >> 2, tid = lane & 3;

    uint32_t asBase = (uint32_t)__cvta_generic_to_shared(Asm);
    uint32_t bsBase = (uint32_t)__cvta_generic_to_shared(Bsm);

    auto issue = [&](int kt, int buf) {
        int kc = kt * 32;
        int h = kc >> 5;
#pragma unroll
        for (int p = 0; p < 4; p++) {
            int idx = t + p * 128;
            int row = idx >> 3, c4 = (idx & 7) * 4;
            int m = bM + row;
            int s = m >> 8, rr = m & 255;
            cp16(asBase + (buf * AS_WORDS + row * AS_STRIDE + c4) * 4,
                 g_O + ((s * 8 + h) * 256 + rr) * 32 + c4);
        }
#pragma unroll
        for (int p = 0; p < 16; p++) {
            int idx = t + p * 128;
            int br = idx >> 6, bc = (idx & 63) * 4;
            cp16(bsBase + (buf * BS_WORDS + br * BS_STRIDE + bc) * 4,
                 w_o + (kc + br) * 256 + bc);
        }
        cp_commit();
    };

    float acc[4][8][4];
#pragma unroll
    for (int i = 0; i < 4; i++)
#pragma unroll
        for (int j = 0; j < 8; j++)
#pragma unroll
            for (int r = 0; r < 4; r++) acc[i][j][r] = 0.f;

    issue(0, 0);

    for (int kt = 0; kt < 8; kt++) {
        int cur = kt & 1;
        if (kt < 7) { issue(kt + 1, cur ^ 1); cp_wait<1>(); }
        else        { cp_wait<0>(); }
        __syncthreads();
        gemm_chunk(Asm + cur * AS_WORDS, Bsm + cur * BS_WORDS,
                   w, gid, tid, acc);
        __syncthreads();
    }

#pragma unroll
    for (int i = 0; i < 4; i++) {
#pragma unroll
        for (int j = 0; j < 8; j++) {
            int r0 = bM + i * 16 + gid;
            int c0 = w * 64 + j * 8 + tid * 2;
#pragma unroll
            for (int e = 0; e < 4; e++) {
                int row = r0 + (e >> 1) * 8;
                int col = c0 + (e & 1);
                out[row * 256 + col] = acc[i][j][e] + b_o[col];
            }
        }
    }
}

// ---------------------------------------------------------------------------
extern "C" void kernel_launch(void* const* d_in, const int* in_sizes, int n_in,
                              void* d_out, int out_size) {
    const float* q    = (const float*)d_in[0];
    const float* kv   = (const float*)d_in[1];
    const float* bias = (const float*)d_in[2];
    const float* mask = (const float*)d_in[3];
    const float* w_q  = (const float*)d_in[4];
    const float* w_k  = (const float*)d_in[5];
    const float* w_v  = (const float*)d_in[6];
    const float* w_g  = (const float*)d_in[7];
    const float* b_g  = (const float*)d_in[8];
    const float* w_o  = (const float*)d_in[9];
    const float* b_o  = (const float*)d_in[10];
    float* out = (float*)d_out;

    bias_transpose_kernel<<<(H_DIM * R_DIM * R_DIM + 255) / 256, 256>>>(bias);

    cudaFuncSetAttribute(proj_mma_kernel,
                         cudaFuncAttributeMaxDynamicSharedMemorySize,
                         GEMM_SMEM_BYTES);
    proj_mma_kernel<<<dim3(SR_DIM / 64, 4), 128, GEMM_SMEM_BYTES>>>(
        q, kv, w_q, w_k, w_v, w_g, b_g);

    const int ATTN_SMEM = ATTN_SMEM_WORDS * 4;   // 140800 B
    cudaFuncSetAttribute(attn_mma_kernel,
                         cudaFuncAttributeMaxDynamicSharedMemorySize, ATTN_SMEM);
    attn_mma_kernel<<<dim3(S_DIM, H_DIM), 256, ATTN_SMEM>>>(mask);

    cudaFuncSetAttribute(outproj_mma_kernel,
                         cudaFuncAttributeMaxDynamicSharedMemorySize,
                         GEMM_SMEM_BYTES);
    outproj_mma_kernel<<<SR_DIM / 64, 128, GEMM_SMEM_BYTES>>>(w_o, b_o, out);
}